// round 10
// baseline (speedup 1.0000x reference)
#include <cuda_runtime.h>
#include <cuda_bf16.h>

#define S_LEN 512
#define B_DIM 256
#define Z_DIM 64

// Plain-FFMA dot of the 64-float smem vector against 64 register coeffs,
// 4 independent accumulator chains, float4 (LDS.128 broadcast) reads.
// Measured best per-step formulation (R2: 174 cy/step).
#define DOT64(VR, result)                                                      \
    {                                                                          \
        const float4* a4 = reinterpret_cast<const float4*>(VR);                \
        float c0 = 0.f, c1 = 0.f, c2 = 0.f, c3 = 0.f;                          \
        _Pragma("unroll")                                                      \
        for (int k = 0; k < Z_DIM / 4; k++) {                                  \
            float4 v = a4[k];                                                  \
            c0 = fmaf(v.x, Tr[4 * k + 0], c0);                                 \
            c1 = fmaf(v.y, Tr[4 * k + 1], c1);                                 \
            c2 = fmaf(v.z, Tr[4 * k + 2], c2);                                 \
            c3 = fmaf(v.w, Tr[4 * k + 3], c3);                                 \
        }                                                                      \
        result = (c0 + c1) + (c2 + c3);                                        \
    }

// ---------------------------------------------------------------------------
// Forward: alpha[t] = e[t] * (alpha[t-1] @ T^T). 256 CTAs x 64 threads.
// Thread s holds ROW s of T in registers. Double-buffered smem vector,
// ONE barrier per step, 2x time-unroll (static names), 2-deep emit prefetch.
// ---------------------------------------------------------------------------
__global__ __launch_bounds__(Z_DIM)
void hmm_fwd_kernel(const int* __restrict__ inp,      // [S, B]
                    const float* __restrict__ T,      // [Z, Z]
                    const float* __restrict__ pi,     // [Z]
                    const float* __restrict__ emit,   // [X, Z]
                    float* __restrict__ alpha)        // [S, B, Z]
{
    const int b = blockIdx.x;
    const int s = threadIdx.x;

    __shared__ __align__(16) float v_sh[2][Z_DIM];
    __shared__ int x_sh[S_LEN];

    #pragma unroll
    for (int t = s; t < S_LEN; t += Z_DIM) x_sh[t] = inp[t * B_DIM + b];

    float Tr[Z_DIM];                     // row s of T
    #pragma unroll
    for (int k = 0; k < Z_DIM; k += 4) {
        float4 v = *reinterpret_cast<const float4*>(&T[s * Z_DIM + k]);
        Tr[k] = v.x; Tr[k+1] = v.y; Tr[k+2] = v.z; Tr[k+3] = v.w;
    }
    __syncthreads();                     // x_sh visible before any use

    float* aw = alpha + (size_t)b * Z_DIM;
    float a0 = emit[x_sh[0] * Z_DIM + s] * pi[s];
    aw[s] = a0;
    v_sh[0][s] = a0;
    float eo = emit[x_sh[1] * Z_DIM + s];   // e for odd steps
    float ee = emit[x_sh[2] * Z_DIM + s];   // e for even steps
    __syncthreads();

#define FWD_STEP(t, VR, VW, E)                                                 \
    {                                                                          \
        int xp = x_sh[((t) + 2 < S_LEN) ? (t) + 2 : S_LEN - 1] * Z_DIM;        \
        float d; DOT64(VR, d);                                                 \
        float n = (E) * d;                                                     \
        E = emit[xp + s];                                                      \
        aw[(size_t)(t) * B_DIM * Z_DIM + s] = n;                               \
        (VW)[s] = n;                                                           \
        __syncthreads();                                                       \
    }

    for (int t = 1; t < S_LEN - 1; t += 2) {
        FWD_STEP(t,     v_sh[0], v_sh[1], eo);
        FWD_STEP(t + 1, v_sh[1], v_sh[0], ee);
    }
    FWD_STEP(S_LEN - 1, v_sh[0], v_sh[1], eo);
#undef FWD_STEP
}

// ---------------------------------------------------------------------------
// Backward: c[t+1]=e[t+1]*beta[t+1]; beta[t] = c[t+1] @ T. 256 CTAs x 64 thr.
// Thread s holds COLUMN s of T. Same single-barrier double-buffer scheme.
// Step t reads buf[(t+1)&1], writes c[t] into buf[t&1].
// ---------------------------------------------------------------------------
__global__ __launch_bounds__(Z_DIM)
void hmm_bwd_kernel(const int* __restrict__ inp,
                    const float* __restrict__ T,
                    const float* __restrict__ emit,
                    float* __restrict__ beta)         // [S, B, Z]
{
    const int b = blockIdx.x;
    const int s = threadIdx.x;

    __shared__ __align__(16) float v_sh[2][Z_DIM];
    __shared__ int x_sh[S_LEN];

    #pragma unroll
    for (int t = s; t < S_LEN; t += Z_DIM) x_sh[t] = inp[t * B_DIM + b];

    float Tr[Z_DIM];                     // column s of T (coalesced per k)
    #pragma unroll
    for (int k = 0; k < Z_DIM; k++) Tr[k] = T[k * Z_DIM + s];
    __syncthreads();                     // x_sh visible before any use

    float* bw = beta + (size_t)b * Z_DIM;
    bw[(size_t)(S_LEN - 1) * B_DIM * Z_DIM + s] = 1.0f;
    v_sh[1][s] = emit[x_sh[S_LEN - 1] * Z_DIM + s];   // c[511] (511&1==1)
    float ee = emit[x_sh[S_LEN - 2] * Z_DIM + s];     // e for even steps
    float eo = emit[x_sh[S_LEN - 3] * Z_DIM + s];     // e for odd steps
    __syncthreads();

#define BWD_STEP(t, VR, VW, E)                                                 \
    {                                                                          \
        int xp = x_sh[((t) >= 2) ? (t) - 2 : 0] * Z_DIM;                       \
        float d; DOT64(VR, d);                                                 \
        bw[(size_t)(t) * B_DIM * Z_DIM + s] = d;                               \
        (VW)[s] = (E) * d;                                                     \
        E = emit[xp + s];                                                      \
        __syncthreads();                                                       \
    }

    for (int t = S_LEN - 2; t >= 2; t -= 2) {
        BWD_STEP(t,     v_sh[1], v_sh[0], ee);   // even t: read buf1 -> buf0
        BWD_STEP(t - 1, v_sh[0], v_sh[1], eo);   // odd  t: read buf0 -> buf1
    }
    {   // t = 0: beta only
        float d; DOT64(v_sh[1], d);
        bw[s] = d;
    }
#undef BWD_STEP
}

// ---------------------------------------------------------------------------
// Posterior: post = alpha*beta / sum_z(alpha*beta). Streaming, HBM-bound.
// ---------------------------------------------------------------------------
__global__ __launch_bounds__(256)
void hmm_post_kernel(const float* __restrict__ alpha,
                     const float* __restrict__ beta,
                     float* __restrict__ post)
{
    const int gid = blockIdx.x * blockDim.x + threadIdx.x;
    const int row = gid >> 4;
    const int sub = gid & 15;

    const size_t off = (size_t)row * Z_DIM + sub * 4;
    float4 av = *reinterpret_cast<const float4*>(alpha + off);
    float4 bv = *reinterpret_cast<const float4*>(beta  + off);

    float4 ab;
    ab.x = av.x * bv.x; ab.y = av.y * bv.y;
    ab.z = av.z * bv.z; ab.w = av.w * bv.w;

    float sm = (ab.x + ab.y) + (ab.z + ab.w);
    #pragma unroll
    for (int o = 8; o > 0; o >>= 1) sm += __shfl_xor_sync(0xffffffffu, sm, o);

    float inv = 1.0f / sm;
    float4 p;
    p.x = ab.x * inv; p.y = ab.y * inv; p.z = ab.z * inv; p.w = ab.w * inv;
    *reinterpret_cast<float4*>(post + off) = p;
}

extern "C" void kernel_launch(void* const* d_in, const int* in_sizes, int n_in,
                              void* d_out, int out_size)
{
    const int*   inp  = (const int*)  d_in[0];   // [512, 256] int32
    const float* T    = (const float*)d_in[1];   // [64, 64]
    const float* pi   = (const float*)d_in[2];   // [64]
    const float* emit = (const float*)d_in[3];   // [10000, 64]

    float* out   = (float*)d_out;
    const size_t N = (size_t)S_LEN * B_DIM * Z_DIM;
    float* alpha = out;
    float* beta  = out + N;
    float* post  = out + 2 * N;

    hmm_fwd_kernel<<<B_DIM, Z_DIM>>>(inp, T, pi, emit, alpha);
    hmm_bwd_kernel<<<B_DIM, Z_DIM>>>(inp, T, emit, beta);

    const int rows = S_LEN * B_DIM;             // 131072
    hmm_post_kernel<<<rows * 16 / 256, 256>>>(alpha, beta, post);
}

// round 11
// speedup vs baseline: 1.4959x; 1.4959x over previous
#include <cuda_runtime.h>
#include <cuda_bf16.h>

#define S_LEN 512
#define B_DIM 256
#define Z_DIM 64

// ---- packed f32x2 helpers (full fp32 precision, 2 MACs per instruction) ----
__device__ __forceinline__ unsigned long long pack2(float lo, float hi) {
    unsigned long long r;
    asm("mov.b64 %0, {%1, %2};" : "=l"(r) : "f"(lo), "f"(hi));
    return r;
}
__device__ __forceinline__ unsigned long long fma2(unsigned long long a,
                                                   unsigned long long b,
                                                   unsigned long long c) {
    unsigned long long d;
    asm("fma.rn.f32x2 %0, %1, %2, %3;" : "=l"(d) : "l"(a), "l"(b), "l"(c));
    return d;
}
__device__ __forceinline__ unsigned long long add2(unsigned long long a,
                                                   unsigned long long b) {
    unsigned long long d;
    asm("add.rn.f32x2 %0, %1, %2;" : "=l"(d) : "l"(a), "l"(b));
    return d;
}
__device__ __forceinline__ float hsum2(unsigned long long v) {
    float lo, hi;
    asm("mov.b64 {%0, %1}, %2;" : "=f"(lo), "=f"(hi) : "l"(v));
    return lo + hi;
}

// FFMA2 dot: 64-float smem vector (16 LDS.128) vs 32 packed T pairs in regs,
// 8 independent f32x2 chains of depth 4 (short RAW chains). R5-measured best.
#define DOT64(VR, result)                                                      \
    {                                                                          \
        const ulonglong2* p2 = reinterpret_cast<const ulonglong2*>(VR);        \
        unsigned long long s0 = 0, s1 = 0, s2 = 0, s3 = 0,                     \
                           s4 = 0, s5 = 0, s6 = 0, s7 = 0;                     \
        _Pragma("unroll")                                                      \
        for (int q = 0; q < 4; q++) {                                          \
            ulonglong2 u0 = p2[4 * q + 0];                                     \
            ulonglong2 u1 = p2[4 * q + 1];                                     \
            ulonglong2 u2 = p2[4 * q + 2];                                     \
            ulonglong2 u3 = p2[4 * q + 3];                                     \
            s0 = fma2(u0.x, Tp[8 * q + 0], s0);                                \
            s1 = fma2(u0.y, Tp[8 * q + 1], s1);                                \
            s2 = fma2(u1.x, Tp[8 * q + 2], s2);                                \
            s3 = fma2(u1.y, Tp[8 * q + 3], s3);                                \
            s4 = fma2(u2.x, Tp[8 * q + 4], s4);                                \
            s5 = fma2(u2.y, Tp[8 * q + 5], s5);                                \
            s6 = fma2(u3.x, Tp[8 * q + 6], s6);                                \
            s7 = fma2(u3.y, Tp[8 * q + 7], s7);                                \
        }                                                                      \
        unsigned long long sA = add2(add2(s0, s1), add2(s2, s3));              \
        unsigned long long sB = add2(add2(s4, s5), add2(s6, s7));              \
        result = hsum2(add2(sA, sB));                                          \
    }

// ---------------------------------------------------------------------------
// Fused forward/backward (concurrent, independent). 512 CTAs x 64 threads.
//   blocks [0,256):   alpha[t] = e[t] * (alpha[t-1] @ T^T)  (thread z: row z)
//   blocks [256,512): beta[t]  = (e[t+1]*beta[t+1]) @ T     (thread z: col z)
// Double-buffered smem vector, ONE barrier per step, 2x time-unroll so all
// buffer/prefetch names are STATIC registers (no local memory — R5's e_ring
// was runtime-indexed and spilled to LDL/STL on the critical path).
// Streaming stores (__stcs) for the 96MB write-once outputs.
// ---------------------------------------------------------------------------
__global__ __launch_bounds__(Z_DIM)
void hmm_fb_kernel(const int* __restrict__ inp,      // [S, B]
                   const float* __restrict__ T,      // [Z, Z]
                   const float* __restrict__ pi,     // [Z]
                   const float* __restrict__ emit,   // [X, Z]
                   float* __restrict__ alpha,        // [S, B, Z]
                   float* __restrict__ beta)         // [S, B, Z]
{
    const bool bwd = blockIdx.x >= B_DIM;
    const int  b   = blockIdx.x & (B_DIM - 1);
    const int  z   = threadIdx.x;

    __shared__ __align__(16) float v_sh[2][Z_DIM];
    __shared__ int x_sh[S_LEN];

    #pragma unroll
    for (int t = z; t < S_LEN; t += Z_DIM) x_sh[t] = inp[t * B_DIM + b];

    // T packed K-pairwise: fwd row z, bwd column z.
    unsigned long long Tp[Z_DIM / 2];
    if (!bwd) {
        #pragma unroll
        for (int k = 0; k < Z_DIM; k += 4) {
            float4 v = *reinterpret_cast<const float4*>(&T[z * Z_DIM + k]);
            Tp[k / 2]     = pack2(v.x, v.y);
            Tp[k / 2 + 1] = pack2(v.z, v.w);
        }
    } else {
        #pragma unroll
        for (int k = 0; k < Z_DIM; k += 2) {
            Tp[k / 2] = pack2(T[k * Z_DIM + z], T[(k + 1) * Z_DIM + z]);
        }
    }
    __syncthreads();            // x_sh visible before any use

    if (!bwd) {
        // ---------------- forward ----------------
        float* aw = alpha + (size_t)b * Z_DIM;
        float a0 = emit[x_sh[0] * Z_DIM + z] * pi[z];
        __stcs(&aw[z], a0);
        v_sh[0][z] = a0;
        float eo = emit[x_sh[1] * Z_DIM + z];   // e for odd steps
        float ee = emit[x_sh[2] * Z_DIM + z];   // e for even steps
        __syncthreads();

#define FWD_STEP(t, VR, VW, E)                                                 \
    {                                                                          \
        int xp = x_sh[((t) + 2 < S_LEN) ? (t) + 2 : S_LEN - 1] * Z_DIM;        \
        float d; DOT64(VR, d);                                                 \
        float n = (E) * d;                                                     \
        E = emit[xp + z];                                                      \
        __stcs(&aw[(size_t)(t) * B_DIM * Z_DIM + z], n);                       \
        (VW)[z] = n;                                                           \
        __syncthreads();                                                       \
    }

        for (int t = 1; t < S_LEN - 1; t += 2) {
            FWD_STEP(t,     v_sh[0], v_sh[1], eo);
            FWD_STEP(t + 1, v_sh[1], v_sh[0], ee);
        }
        FWD_STEP(S_LEN - 1, v_sh[0], v_sh[1], eo);
#undef FWD_STEP
    } else {
        // ---------------- backward ----------------
        float* bw = beta + (size_t)b * Z_DIM;
        __stcs(&bw[(size_t)(S_LEN - 1) * B_DIM * Z_DIM + z], 1.0f);
        v_sh[1][z] = emit[x_sh[S_LEN - 1] * Z_DIM + z];   // c[511] (511&1==1)
        float ee = emit[x_sh[S_LEN - 2] * Z_DIM + z];     // e for even steps
        float eo = emit[x_sh[S_LEN - 3] * Z_DIM + z];     // e for odd steps
        __syncthreads();

#define BWD_STEP(t, VR, VW, E)                                                 \
    {                                                                          \
        int xp = x_sh[((t) >= 2) ? (t) - 2 : 0] * Z_DIM;                       \
        float d; DOT64(VR, d);                                                 \
        __stcs(&bw[(size_t)(t) * B_DIM * Z_DIM + z], d);                       \
        (VW)[z] = (E) * d;                                                     \
        E = emit[xp + z];                                                      \
        __syncthreads();                                                       \
    }

        for (int t = S_LEN - 2; t >= 2; t -= 2) {
            BWD_STEP(t,     v_sh[1], v_sh[0], ee);   // even t: buf1 -> buf0
            BWD_STEP(t - 1, v_sh[0], v_sh[1], eo);   // odd  t: buf0 -> buf1
        }
        {   // t = 0: beta only (reads c[1] in buf1)
            float d; DOT64(v_sh[1], d);
            __stcs(&bw[z], d);
        }
#undef BWD_STEP
    }
}

// ---------------------------------------------------------------------------
// Posterior: post = alpha*beta / sum_z(alpha*beta). Streaming, HBM-bound.
// ---------------------------------------------------------------------------
__global__ __launch_bounds__(256)
void hmm_post_kernel(const float* __restrict__ alpha,
                     const float* __restrict__ beta,
                     float* __restrict__ post)
{
    const int gid = blockIdx.x * blockDim.x + threadIdx.x;
    const int row = gid >> 4;
    const int sub = gid & 15;

    const size_t off = (size_t)row * Z_DIM + sub * 4;
    float4 av = __ldcs(reinterpret_cast<const float4*>(alpha + off));
    float4 bv = __ldcs(reinterpret_cast<const float4*>(beta  + off));

    float4 ab;
    ab.x = av.x * bv.x; ab.y = av.y * bv.y;
    ab.z = av.z * bv.z; ab.w = av.w * bv.w;

    float sm = (ab.x + ab.y) + (ab.z + ab.w);
    #pragma unroll
    for (int o = 8; o > 0; o >>= 1) sm += __shfl_xor_sync(0xffffffffu, sm, o);

    float inv = 1.0f / sm;
    float4 p;
    p.x = ab.x * inv; p.y = ab.y * inv; p.z = ab.z * inv; p.w = ab.w * inv;
    __stcs(reinterpret_cast<float4*>(post + off), p);
}

extern "C" void kernel_launch(void* const* d_in, const int* in_sizes, int n_in,
                              void* d_out, int out_size)
{
    const int*   inp  = (const int*)  d_in[0];   // [512, 256] int32
    const float* T    = (const float*)d_in[1];   // [64, 64]
    const float* pi   = (const float*)d_in[2];   // [64]
    const float* emit = (const float*)d_in[3];   // [10000, 64]

    float* out   = (float*)d_out;
    const size_t N = (size_t)S_LEN * B_DIM * Z_DIM;
    float* alpha = out;
    float* beta  = out + N;
    float* post  = out + 2 * N;

    hmm_fb_kernel<<<2 * B_DIM, Z_DIM>>>(inp, T, pi, emit, alpha, beta);

    const int rows = S_LEN * B_DIM;             // 131072
    hmm_post_kernel<<<rows * 16 / 256, 256>>>(alpha, beta, post);
}

// round 12
// speedup vs baseline: 1.8765x; 1.2544x over previous
#include <cuda_runtime.h>
#include <cuda_bf16.h>

#define S_LEN 512
#define B_DIM 256
#define Z_DIM 64

// ---- packed f32x2 helpers (full fp32 precision, 2 MACs per instruction) ----
__device__ __forceinline__ unsigned long long pack2(float lo, float hi) {
    unsigned long long r;
    asm("mov.b64 %0, {%1, %2};" : "=l"(r) : "f"(lo), "f"(hi));
    return r;
}
__device__ __forceinline__ unsigned long long fma2(unsigned long long a,
                                                   unsigned long long b,
                                                   unsigned long long c) {
    unsigned long long d;
    asm("fma.rn.f32x2 %0, %1, %2, %3;" : "=l"(d) : "l"(a), "l"(b), "l"(c));
    return d;
}
__device__ __forceinline__ unsigned long long add2(unsigned long long a,
                                                   unsigned long long b) {
    unsigned long long d;
    asm("add.rn.f32x2 %0, %1, %2;" : "=l"(d) : "l"(a), "l"(b));
    return d;
}
__device__ __forceinline__ float hsum2(unsigned long long v) {
    float lo, hi;
    asm("mov.b64 {%0, %1}, %2;" : "=f"(lo), "=f"(hi) : "l"(v));
    return lo + hi;
}

// FFMA2 dot: 64-float smem vector (16 LDS.128) vs 32 packed T pairs in regs,
// 8 independent f32x2 chains of depth 4.
#define DOT64(VR, result)                                                      \
    {                                                                          \
        const ulonglong2* p2 = reinterpret_cast<const ulonglong2*>(VR);        \
        unsigned long long s0 = 0, s1 = 0, s2 = 0, s3 = 0,                     \
                           s4 = 0, s5 = 0, s6 = 0, s7 = 0;                     \
        _Pragma("unroll")                                                      \
        for (int q = 0; q < 4; q++) {                                          \
            ulonglong2 u0 = p2[4 * q + 0];                                     \
            ulonglong2 u1 = p2[4 * q + 1];                                     \
            ulonglong2 u2 = p2[4 * q + 2];                                     \
            ulonglong2 u3 = p2[4 * q + 3];                                     \
            s0 = fma2(u0.x, Tp[8 * q + 0], s0);                                \
            s1 = fma2(u0.y, Tp[8 * q + 1], s1);                                \
            s2 = fma2(u1.x, Tp[8 * q + 2], s2);                                \
            s3 = fma2(u1.y, Tp[8 * q + 3], s3);                                \
            s4 = fma2(u2.x, Tp[8 * q + 4], s4);                                \
            s5 = fma2(u2.y, Tp[8 * q + 5], s5);                                \
            s6 = fma2(u3.x, Tp[8 * q + 6], s6);                                \
            s7 = fma2(u3.y, Tp[8 * q + 7], s7);                                \
        }                                                                      \
        unsigned long long sA = add2(add2(s0, s1), add2(s2, s3));              \
        unsigned long long sB = add2(add2(s4, s5), add2(s6, s7));              \
        result = hsum2(add2(sA, sB));                                          \
    }

// ---------------------------------------------------------------------------
// Fused forward/backward (concurrent, independent). 512 CTAs x 64 threads.
//   blocks [0,256):   alpha[t] = e[t] * (alpha[t-1] @ T^T)  (thread z: row z)
//   blocks [256,512): beta[t]  = (e[t+1]*beta[t+1]) @ T     (thread z: col z)
// Double-buffered smem vector, ONE barrier per step.
// CRITICAL-PATH ORDERING: only DOT -> (mul) -> STS precede the barrier;
// the output STG (stcs) and the emission-prefetch LDG are issued AFTER the
// barrier so they overlap the next step's LDS latency instead of delaying
// the barrier release.
// ---------------------------------------------------------------------------
__global__ __launch_bounds__(Z_DIM)
void hmm_fb_kernel(const int* __restrict__ inp,      // [S, B]
                   const float* __restrict__ T,      // [Z, Z]
                   const float* __restrict__ pi,     // [Z]
                   const float* __restrict__ emit,   // [X, Z]
                   float* __restrict__ alpha,        // [S, B, Z]
                   float* __restrict__ beta)         // [S, B, Z]
{
    const bool bwd = blockIdx.x >= B_DIM;
    const int  b   = blockIdx.x & (B_DIM - 1);
    const int  z   = threadIdx.x;

    __shared__ __align__(16) float v_sh[2][Z_DIM];
    __shared__ int x_sh[S_LEN];

    #pragma unroll
    for (int t = z; t < S_LEN; t += Z_DIM) x_sh[t] = inp[t * B_DIM + b];

    // T packed K-pairwise: fwd row z, bwd column z.
    unsigned long long Tp[Z_DIM / 2];
    if (!bwd) {
        #pragma unroll
        for (int k = 0; k < Z_DIM; k += 4) {
            float4 v = *reinterpret_cast<const float4*>(&T[z * Z_DIM + k]);
            Tp[k / 2]     = pack2(v.x, v.y);
            Tp[k / 2 + 1] = pack2(v.z, v.w);
        }
    } else {
        #pragma unroll
        for (int k = 0; k < Z_DIM; k += 2) {
            Tp[k / 2] = pack2(T[k * Z_DIM + z], T[(k + 1) * Z_DIM + z]);
        }
    }
    __syncthreads();            // x_sh visible before any use

    if (!bwd) {
        // ---------------- forward ----------------
        float* aw = alpha + (size_t)b * Z_DIM;
        float a0 = emit[x_sh[0] * Z_DIM + z] * pi[z];
        __stcs(&aw[z], a0);
        v_sh[0][z] = a0;
        float eo = emit[x_sh[1] * Z_DIM + z];   // e for odd steps
        float ee = emit[x_sh[2] * Z_DIM + z];   // e for even steps
        float pend = 0.f;                        // value pending STG
        size_t pofs = 0;                         // its offset (dummy before t=1)
        bool   has_pend = false;
        __syncthreads();

#define FWD_STEP(t, VR, VW, E)                                                 \
    {                                                                          \
        float d; DOT64(VR, d);                                                 \
        float n = (E) * d;                                                     \
        (VW)[z] = n;                                                           \
        __syncthreads();                                                       \
        /* post-barrier shadow work */                                         \
        if (has_pend) __stcs(&aw[pofs], pend);                                 \
        pend = n; pofs = (size_t)(t) * B_DIM * Z_DIM + z; has_pend = true;     \
        int xp = x_sh[((t) + 2 < S_LEN) ? (t) + 2 : S_LEN - 1] * Z_DIM;        \
        E = emit[xp + z];                                                      \
    }

        for (int t = 1; t < S_LEN - 1; t += 2) {
            FWD_STEP(t,     v_sh[0], v_sh[1], eo);
            FWD_STEP(t + 1, v_sh[1], v_sh[0], ee);
        }
        FWD_STEP(S_LEN - 1, v_sh[0], v_sh[1], eo);
        __stcs(&aw[pofs], pend);                 // flush last pending store
#undef FWD_STEP
    } else {
        // ---------------- backward ----------------
        float* bw = beta + (size_t)b * Z_DIM;
        __stcs(&bw[(size_t)(S_LEN - 1) * B_DIM * Z_DIM + z], 1.0f);
        v_sh[1][z] = emit[x_sh[S_LEN - 1] * Z_DIM + z];   // c[511] (511&1==1)
        float ee = emit[x_sh[S_LEN - 2] * Z_DIM + z];     // e for even steps
        float eo = emit[x_sh[S_LEN - 3] * Z_DIM + z];     // e for odd steps
        float pend = 0.f;
        size_t pofs = 0;
        bool   has_pend = false;
        __syncthreads();

#define BWD_STEP(t, VR, VW, E)                                                 \
    {                                                                          \
        float d; DOT64(VR, d);                                                 \
        (VW)[z] = (E) * d;                                                     \
        __syncthreads();                                                       \
        /* post-barrier shadow work */                                         \
        if (has_pend) __stcs(&bw[pofs], pend);                                 \
        pend = d; pofs = (size_t)(t) * B_DIM * Z_DIM + z; has_pend = true;     \
        int xp = x_sh[((t) >= 2) ? (t) - 2 : 0] * Z_DIM;                       \
        E = emit[xp + z];                                                      \
    }

        for (int t = S_LEN - 2; t >= 2; t -= 2) {
            BWD_STEP(t,     v_sh[1], v_sh[0], ee);   // even t: buf1 -> buf0
            BWD_STEP(t - 1, v_sh[0], v_sh[1], eo);   // odd  t: buf0 -> buf1
        }
        __stcs(&bw[pofs], pend);                 // flush pending (t=1)
        {   // t = 0: beta only (reads c[1] in buf1)
            float d; DOT64(v_sh[1], d);
            __stcs(&bw[z], d);
        }
#undef BWD_STEP
    }
}

// ---------------------------------------------------------------------------
// Posterior: post = alpha*beta / sum_z(alpha*beta). Streaming, HBM-bound.
// ---------------------------------------------------------------------------
__global__ __launch_bounds__(256)
void hmm_post_kernel(const float* __restrict__ alpha,
                     const float* __restrict__ beta,
                     float* __restrict__ post)
{
    const int gid = blockIdx.x * blockDim.x + threadIdx.x;
    const int row = gid >> 4;
    const int sub = gid & 15;

    const size_t off = (size_t)row * Z_DIM + sub * 4;
    float4 av = __ldcs(reinterpret_cast<const float4*>(alpha + off));
    float4 bv = __ldcs(reinterpret_cast<const float4*>(beta  + off));

    float4 ab;
    ab.x = av.x * bv.x; ab.y = av.y * bv.y;
    ab.z = av.z * bv.z; ab.w = av.w * bv.w;

    float sm = (ab.x + ab.y) + (ab.z + ab.w);
    #pragma unroll
    for (int o = 8; o > 0; o >>= 1) sm += __shfl_xor_sync(0xffffffffu, sm, o);

    float inv = 1.0f / sm;
    float4 p;
    p.x = ab.x * inv; p.y = ab.y * inv; p.z = ab.z * inv; p.w = ab.w * inv;
    __stcs(reinterpret_cast<float4*>(post + off), p);
}

extern "C" void kernel_launch(void* const* d_in, const int* in_sizes, int n_in,
                              void* d_out, int out_size)
{
    const int*   inp  = (const int*)  d_in[0];   // [512, 256] int32
    const float* T    = (const float*)d_in[1];   // [64, 64]
    const float* pi   = (const float*)d_in[2];   // [64]
    const float* emit = (const float*)d_in[3];   // [10000, 64]

    float* out   = (float*)d_out;
    const size_t N = (size_t)S_LEN * B_DIM * Z_DIM;
    float* alpha = out;
    float* beta  = out + N;
    float* post  = out + 2 * N;

    hmm_fb_kernel<<<2 * B_DIM, Z_DIM>>>(inp, T, pi, emit, alpha, beta);

    const int rows = S_LEN * B_DIM;             // 131072
    hmm_post_kernel<<<rows * 16 / 256, 256>>>(alpha, beta, post);
}